// round 3
// baseline (speedup 1.0000x reference)
#include <cuda_runtime.h>

// Problem constants (dataset is fixed; runtime sizes passed to kernels as guards)
#define MAXN 100000
#define NHID 32

// ---- device scratch (no allocations allowed) ----
__device__ float  g_deg [MAXN];
__device__ float  g_dinv[MAXN];
__device__ float4 g_xp  [MAXN];       // x padded to 4 (w = 0)
__device__ float4 g_aggx[MAXN];       // layer-0 aggregation of raw x
__device__ float4 g_h4  [MAXN * 8];   // h1 = relu(aggx@W0 + b0)   [N x 32]
__device__ float4 g_agg4[MAXN * 8];   // layer-1 aggregation of h1 [N x 32]

// Native vector atomic (cc >= 9.0): nvcc handles generic->global conversion
__device__ __forceinline__ void red_add_v4(float4* addr, float4 v) {
    atomicAdd(addr, v);
}

// K1: deg starts at 1.0 (self-loop weight)
__global__ void k_init(int n) {
    int i = blockIdx.x * blockDim.x + threadIdx.x;
    if (i < n) g_deg[i] = 1.0f;
}

// K2: deg[col] += w  over all edges  (edge_index is int32!)
__global__ void k_deg(const int* __restrict__ idx, const float* __restrict__ w, int E) {
    int e = blockIdx.x * blockDim.x + threadIdx.x;
    if (e >= E) return;
    int col = idx[E + e];
    atomicAdd(&g_deg[col], w[e]);
}

// K3: dinv = rsqrt(deg); stage padded x; seed layer-0 agg with self-loop term x*dinv^2
__global__ void k_dinv(const float* __restrict__ x, int n) {
    int i = blockIdx.x * blockDim.x + threadIdx.x;
    if (i >= n) return;
    float d  = g_deg[i];
    float dv = d > 0.f ? rsqrtf(d) : 0.f;
    g_dinv[i] = dv;
    float x0 = x[3 * i], x1 = x[3 * i + 1], x2 = x[3 * i + 2];
    g_xp[i] = make_float4(x0, x1, x2, 0.f);
    float s = dv * dv;
    g_aggx[i] = make_float4(x0 * s, x1 * s, x2 * s, 0.f);
}

// K4: layer-0 edge pass — aggregate RAW x (linearity: apply W0 after aggregation)
__global__ void k_edge0(const int* __restrict__ idx, const float* __restrict__ w, int E) {
    int e = blockIdx.x * blockDim.x + threadIdx.x;
    if (e >= E) return;
    int row = idx[e];
    int col = idx[E + e];
    float norm = g_dinv[row] * w[e] * g_dinv[col];
    float4 v = g_xp[row];
    red_add_v4(&g_aggx[col], make_float4(v.x * norm, v.y * norm, v.z * norm, 0.f));
}

// K5: h1 = relu(aggx @ W0 + b0); seed layer-1 agg with self-loop term h1*dinv^2.
// Thread per (node, feat-quad) -> fully coalesced float4 writes.
__global__ void k_node0(const float* __restrict__ W0, const float* __restrict__ b0, int n) {
    int t = blockIdx.x * blockDim.x + threadIdx.x;
    if (t >= n * 8) return;
    int i = t >> 3, j = t & 7;
    float4 a  = g_aggx[i];
    float dv  = g_dinv[i];
    float s   = dv * dv;
    float4 w0 = ((const float4*)(W0     ))[j];
    float4 w1 = ((const float4*)(W0 + 32))[j];
    float4 w2 = ((const float4*)(W0 + 64))[j];
    float4 bb = ((const float4*)(b0     ))[j];
    float4 h;
    h.x = fmaf(a.x, w0.x, fmaf(a.y, w1.x, fmaf(a.z, w2.x, bb.x)));
    h.y = fmaf(a.x, w0.y, fmaf(a.y, w1.y, fmaf(a.z, w2.y, bb.y)));
    h.z = fmaf(a.x, w0.z, fmaf(a.y, w1.z, fmaf(a.z, w2.z, bb.z)));
    h.w = fmaf(a.x, w0.w, fmaf(a.y, w1.w, fmaf(a.z, w2.w, bb.w)));
    h.x = fmaxf(h.x, 0.f); h.y = fmaxf(h.y, 0.f);
    h.z = fmaxf(h.z, 0.f); h.w = fmaxf(h.w, 0.f);
    g_h4[t]   = h;
    g_agg4[t] = make_float4(h.x * s, h.y * s, h.z * s, h.w * s);
}

// K6: layer-1 edge pass — gather 32-dim h1[row], vector-red into agg1[col]
__global__ void k_edge1(const int* __restrict__ idx, const float* __restrict__ w, int E) {
    int e = blockIdx.x * blockDim.x + threadIdx.x;
    if (e >= E) return;
    int row = idx[e];
    int col = idx[E + e];
    float norm = g_dinv[row] * w[e] * g_dinv[col];
    const float4* __restrict__ src = g_h4 + row * 8;
    float4* dst = g_agg4 + col * 8;
    float4 v0 = src[0], v1 = src[1], v2 = src[2], v3 = src[3];
    float4 v4 = src[4], v5 = src[5], v6 = src[6], v7 = src[7];
    red_add_v4(dst + 0, make_float4(v0.x * norm, v0.y * norm, v0.z * norm, v0.w * norm));
    red_add_v4(dst + 1, make_float4(v1.x * norm, v1.y * norm, v1.z * norm, v1.w * norm));
    red_add_v4(dst + 2, make_float4(v2.x * norm, v2.y * norm, v2.z * norm, v2.w * norm));
    red_add_v4(dst + 3, make_float4(v3.x * norm, v3.y * norm, v3.z * norm, v3.w * norm));
    red_add_v4(dst + 4, make_float4(v4.x * norm, v4.y * norm, v4.z * norm, v4.w * norm));
    red_add_v4(dst + 5, make_float4(v5.x * norm, v5.y * norm, v5.z * norm, v5.w * norm));
    red_add_v4(dst + 6, make_float4(v6.x * norm, v6.y * norm, v6.z * norm, v6.w * norm));
    red_add_v4(dst + 7, make_float4(v7.x * norm, v7.y * norm, v7.z * norm, v7.w * norm));
}

// K7: per-graph block: h2 = relu(agg1 @ W1 + b1), mean-pool over sorted batch
// range (binary search), head dot with Wr. No global atomics.
__global__ void k_pool(const int* __restrict__ batch,
                       const float* __restrict__ W1, const float* __restrict__ b1,
                       const float* __restrict__ Wr, const float* __restrict__ br,
                       float* __restrict__ out, int n) {
    int g = blockIdx.x;
    __shared__ float sW1[32 * 32];
    __shared__ float sb1[32];
    __shared__ float sWr[32];
    __shared__ int   sse[2];
    __shared__ float stile[8][33];
    __shared__ float spool[8][32];
    int tid = threadIdx.x;  // 256 threads
    for (int k = tid; k < 1024; k += 256) sW1[k] = W1[k];
    if (tid < 32) { sb1[tid] = b1[tid]; sWr[tid] = Wr[tid]; }
    if (tid < 2) {
        int key = g + tid;
        int lo = 0, hi = n;
        while (lo < hi) { int mid = (lo + hi) >> 1; if (batch[mid] < key) lo = mid + 1; else hi = mid; }
        sse[tid] = lo;
    }
    __syncthreads();
    int start = sse[0], end = sse[1];
    int feat = tid & 31, slot = tid >> 5;  // 8 node slots x 32 features
    const float* agg = (const float*)g_agg4;
    float acc = 0.f;
    for (int base = start; base < end; base += 8) {
        int nload = min(8, end - base);
        __syncthreads();
        if (slot < nload) stile[slot][feat] = agg[(base + slot) * 32 + feat];
        __syncthreads();
        if (slot < nload) {
            float v = sb1[feat];
#pragma unroll
            for (int jj = 0; jj < 32; jj++) v = fmaf(stile[slot][jj], sW1[jj * 32 + feat], v);
            acc += fmaxf(v, 0.f);
        }
    }
    spool[slot][feat] = acc;
    __syncthreads();
    if (tid < 32) {
        float s = 0.f;
#pragma unroll
        for (int k = 0; k < 8; k++) s += spool[k][tid];
        float cnt = (float)(end - start);
        float hg = s / fmaxf(cnt, 1.f);
        float p = hg * sWr[tid];
#pragma unroll
        for (int off = 16; off; off >>= 1) p += __shfl_down_sync(0xffffffffu, p, off);
        if (tid == 0) out[g] = p + br[0];
    }
}

extern "C" void kernel_launch(void* const* d_in, const int* in_sizes, int n_in,
                              void* d_out, int out_size) {
    const float* x     = (const float*)d_in[0];
    const int*   ei    = (const int*)d_in[1];      // int32 (JAX x64 disabled)
    const float* ew    = (const float*)d_in[2];
    const int*   batch = (const int*)d_in[3];      // int32
    const float* W0    = (const float*)d_in[4];
    const float* b0    = (const float*)d_in[5];
    const float* W1    = (const float*)d_in[6];
    const float* b1    = (const float*)d_in[7];
    const float* Wr    = (const float*)d_in[8];
    const float* br    = (const float*)d_in[9];
    float* out = (float*)d_out;

    int n = in_sizes[0] / 3;
    int E = in_sizes[2];
    int G = out_size;
    const int TB = 256;

    k_init <<<(n + TB - 1) / TB, TB>>>(n);
    k_deg  <<<(E + TB - 1) / TB, TB>>>(ei, ew, E);
    k_dinv <<<(n + TB - 1) / TB, TB>>>(x, n);
    k_edge0<<<(E + TB - 1) / TB, TB>>>(ei, ew, E);
    k_node0<<<(n * 8 + TB - 1) / TB, TB>>>(W0, b0, n);
    k_edge1<<<(E + TB - 1) / TB, TB>>>(ei, ew, E);
    k_pool <<<G, 256>>>(batch, W1, b1, Wr, br, out, n);
}

// round 4
// speedup vs baseline: 2.8864x; 2.8864x over previous
#include <cuda_runtime.h>

#define MAXN 100000

// ---- device scratch (no allocations allowed) ----
__device__ float g_deg [MAXN];
__device__ float g_dinv[MAXN];
__device__ __align__(128) float4 g_xp  [MAXN];      // xs = dinv*x, padded (w=0)
__device__ __align__(128) float4 g_aggx[MAXN];      // layer-0 agg of xs (seeded w/ self)
__device__ __align__(128) float4 g_h4  [MAXN * 8];  // hs1 = dinv*relu(...)  [N x 32]
__device__ __align__(128) float4 g_agg4[MAXN * 8];  // layer-1 agg of hs1    [N x 32]

__device__ __forceinline__ void red_add_v4(float4* addr, float4 v) {
    atomicAdd(addr, v);   // native vector red (cc >= 9.0)
}

// K1: deg starts at 1.0 (self-loop weight)
__global__ void k_init(int n) {
    int i = blockIdx.x * blockDim.x + threadIdx.x;
    if (i < n) g_deg[i] = 1.0f;
}

// K2: deg[col] += w over all edges (1 random sector/edge)
__global__ void k_deg(const int* __restrict__ idx, const float* __restrict__ w, int E) {
    int e = blockIdx.x * blockDim.x + threadIdx.x;
    if (e >= E) return;
    atomicAdd(&g_deg[idx[E + e]], w[e]);
}

// K3: dinv = rsqrt(deg); xs = dinv*x (pre-scaled source features);
// seed layer-0 agg with the self-loop source term xs (post-scale by dinv later).
__global__ void k_dinv(const float* __restrict__ x, int n) {
    int i = blockIdx.x * blockDim.x + threadIdx.x;
    if (i >= n) return;
    float d  = g_deg[i];
    float dv = d > 0.f ? rsqrtf(d) : 0.f;
    g_dinv[i] = dv;
    float4 xs = make_float4(x[3*i] * dv, x[3*i+1] * dv, x[3*i+2] * dv, 0.f);
    g_xp[i]   = xs;
    g_aggx[i] = xs;
}

// K4: layer-0 edge pass — NO dinv gathers (norm factorized out).
// Per edge: 1 random gather sector + 1 random red sector.
__global__ void k_edge0(const int* __restrict__ idx, const float* __restrict__ w, int E) {
    int e = blockIdx.x * blockDim.x + threadIdx.x;
    if (e >= E) return;
    int row = idx[e];
    int col = idx[E + e];
    float ww = w[e];
    float4 v = g_xp[row];
    red_add_v4(&g_aggx[col], make_float4(v.x * ww, v.y * ww, v.z * ww, 0.f));
}

// K5: apply post-scale dinv, W0, bias, relu; pre-scale h1 by dinv for layer 1;
// seed layer-1 agg with self-loop term hs1. Thread per (node, feat-quad).
__global__ void k_node0(const float* __restrict__ W0, const float* __restrict__ b0, int n) {
    int t = blockIdx.x * blockDim.x + threadIdx.x;
    if (t >= n * 8) return;
    int i = t >> 3, j = t & 7;
    float4 a  = g_aggx[i];
    float dv  = g_dinv[i];
    a.x *= dv; a.y *= dv; a.z *= dv;     // post-scale layer-0 aggregate
    float4 w0 = ((const float4*)(W0     ))[j];
    float4 w1 = ((const float4*)(W0 + 32))[j];
    float4 w2 = ((const float4*)(W0 + 64))[j];
    float4 bb = ((const float4*)(b0     ))[j];
    float4 h;
    h.x = fmaf(a.x, w0.x, fmaf(a.y, w1.x, fmaf(a.z, w2.x, bb.x)));
    h.y = fmaf(a.x, w0.y, fmaf(a.y, w1.y, fmaf(a.z, w2.y, bb.y)));
    h.z = fmaf(a.x, w0.z, fmaf(a.y, w1.z, fmaf(a.z, w2.z, bb.z)));
    h.w = fmaf(a.x, w0.w, fmaf(a.y, w1.w, fmaf(a.z, w2.w, bb.w)));
    // relu then pre-scale by dinv (source scaling for layer 1)
    h.x = fmaxf(h.x, 0.f) * dv; h.y = fmaxf(h.y, 0.f) * dv;
    h.z = fmaxf(h.z, 0.f) * dv; h.w = fmaxf(h.w, 0.f) * dv;
    g_h4[t]   = h;
    g_agg4[t] = h;   // self-loop seed
}

// K6: layer-1 edge pass — 8 lanes per edge, lane j owns feature-quad j.
// Gather + red are coalesced per edge: ~2 wavefronts/edge instead of ~16.
__global__ void k_edge1(const int* __restrict__ idx, const float* __restrict__ w, int E) {
    int t = blockIdx.x * blockDim.x + threadIdx.x;
    int e = t >> 3;
    if (e >= E) return;
    int j   = t & 7;
    int row = idx[e];
    int col = idx[E + e];
    float ww = w[e];
    float4 v = g_h4[row * 8 + j];
    red_add_v4(&g_agg4[col * 8 + j],
               make_float4(v.x * ww, v.y * ww, v.z * ww, v.w * ww));
}

// K7: per-graph block: post-scale agg1 by dinv, h2 = relu(agg1@W1+b1),
// mean-pool over sorted-batch range (binary search), head dot with Wr.
__global__ void k_pool(const int* __restrict__ batch,
                       const float* __restrict__ W1, const float* __restrict__ b1,
                       const float* __restrict__ Wr, const float* __restrict__ br,
                       float* __restrict__ out, int n) {
    int g = blockIdx.x;
    __shared__ float sW1[32 * 32];
    __shared__ float sb1[32];
    __shared__ float sWr[32];
    __shared__ int   sse[2];
    __shared__ float stile[8][33];
    __shared__ float spool[8][32];
    int tid = threadIdx.x;  // 256 threads
    for (int k = tid; k < 1024; k += 256) sW1[k] = W1[k];
    if (tid < 32) { sb1[tid] = b1[tid]; sWr[tid] = Wr[tid]; }
    if (tid < 2) {
        int key = g + tid;
        int lo = 0, hi = n;
        while (lo < hi) { int mid = (lo + hi) >> 1; if (batch[mid] < key) lo = mid + 1; else hi = mid; }
        sse[tid] = lo;
    }
    __syncthreads();
    int start = sse[0], end = sse[1];
    int feat = tid & 31, slot = tid >> 5;  // 8 node slots x 32 features
    const float* agg = (const float*)g_agg4;
    float acc = 0.f;
    for (int base = start; base < end; base += 8) {
        int nload = min(8, end - base);
        __syncthreads();
        if (slot < nload) {
            int node = base + slot;
            stile[slot][feat] = g_dinv[node] * agg[node * 32 + feat];  // post-scale
        }
        __syncthreads();
        if (slot < nload) {
            float v = sb1[feat];
#pragma unroll
            for (int jj = 0; jj < 32; jj++) v = fmaf(stile[slot][jj], sW1[jj * 32 + feat], v);
            acc += fmaxf(v, 0.f);
        }
    }
    spool[slot][feat] = acc;
    __syncthreads();
    if (tid < 32) {
        float s = 0.f;
#pragma unroll
        for (int k = 0; k < 8; k++) s += spool[k][tid];
        float cnt = (float)(end - start);
        float hg = s / fmaxf(cnt, 1.f);
        float p = hg * sWr[tid];
#pragma unroll
        for (int off = 16; off; off >>= 1) p += __shfl_down_sync(0xffffffffu, p, off);
        if (tid == 0) out[g] = p + br[0];
    }
}

extern "C" void kernel_launch(void* const* d_in, const int* in_sizes, int n_in,
                              void* d_out, int out_size) {
    const float* x     = (const float*)d_in[0];
    const int*   ei    = (const int*)d_in[1];
    const float* ew    = (const float*)d_in[2];
    const int*   batch = (const int*)d_in[3];
    const float* W0    = (const float*)d_in[4];
    const float* b0    = (const float*)d_in[5];
    const float* W1    = (const float*)d_in[6];
    const float* b1    = (const float*)d_in[7];
    const float* Wr    = (const float*)d_in[8];
    const float* br    = (const float*)d_in[9];
    float* out = (float*)d_out;

    int n = in_sizes[0] / 3;
    int E = in_sizes[2];
    int G = out_size;
    const int TB = 256;

    k_init <<<(n + TB - 1) / TB, TB>>>(n);
    k_deg  <<<(E + TB - 1) / TB, TB>>>(ei, ew, E);
    k_dinv <<<(n + TB - 1) / TB, TB>>>(x, n);
    k_edge0<<<(E + TB - 1) / TB, TB>>>(ei, ew, E);
    k_node0<<<(n * 8 + TB - 1) / TB, TB>>>(W0, b0, n);
    long long t1 = (long long)E * 8;
    k_edge1<<<(int)((t1 + TB - 1) / TB), TB>>>(ei, ew, E);
    k_pool <<<G, 256>>>(batch, W1, b1, Wr, br, out, n);
}